// round 9
// baseline (speedup 1.0000x reference)
#include <cuda_runtime.h>
#include <cuda_fp16.h>

#define DIM 64
#define DIM2 (DIM / 2)
#define DIM8 (DIM / 4)     // uint2 (8B) chunks per row = 16
#define N_LAYERS 3
#define NODES_MAX 262144
#define EDGES_MAX 16000000
#define SCAN_BLK 1024
#define PARTS_MAX 256      // NODES_MAX / SCAN_BLK

// -------- static device scratch (no allocations allowed) --------
// Referenced ONLY from device code (host-side symbol decay = ATS-backed
// host shadow on GB300 — the silent R2-R4 bug).
__device__ int     g_is64;
__device__ int     g_counts [NODES_MAX];
__device__ int     g_part   [PARTS_MAX];
__device__ int     g_offsets[NODES_MAX + 1];
__device__ int     g_cursor [NODES_MAX];
__device__ int     g_flag   [NODES_MAX];          // 1 if node queried by dot
__device__ int2    g_csr    [EDGES_MAX];          // (src, val-bits) grouped by dst
__device__ __half2 h_bufA   [NODES_MAX * DIM2];   // e0 -> layer-2 output
__device__ __half2 h_bufB   [NODES_MAX * DIM2];   // layer-1 output
__device__ float   g_l3     [NODES_MAX * DIM];    // layer-3 output (flagged rows)

// -------- streaming index load: int32 or int64, evict-first --------
__device__ __forceinline__ int load_idx_cs(const void* p, int i, bool is64) {
    if (is64) return (int)__ldcs((const long long*)p + i);
    return __ldcs((const int*)p + i);
}
__device__ __forceinline__ int load_idx(const void* p, int i, bool is64) {
    if (is64) return (int)((const long long*)p)[i];
    return ((const int*)p)[i];
}

// -------- dtype detection: odd 32-bit words all zero => int64 --------
__global__ void detect_kernel(const unsigned int* __restrict__ p, int nslots) {
    __shared__ unsigned int acc;
    if (threadIdx.x == 0) acc = 0u;
    __syncthreads();
    unsigned int v = 0u;
    for (int s = threadIdx.x; s < nslots; s += 1024) v |= p[2 * s + 1];
    if (v) atomicOr(&acc, 1u);
    __syncthreads();
    if (threadIdx.x == 0) g_is64 = (acc == 0u) ? 1 : 0;
}

// -------- init: h_bufA = fp16(emb); counts = flag = 0 --------
__global__ void init_kernel(const float* __restrict__ ue, const float* __restrict__ ie,
                            int nU2, int nT2, int n_nodes) {
    int i = blockIdx.x * blockDim.x + threadIdx.x;   // float2 index
    if (i < nT2) {
        float2 v = (i < nU2) ? ((const float2*)ue)[i] : ((const float2*)ie)[i - nU2];
        h_bufA[i] = __floats2half2_rn(v.x, v.y);
    }
    if (i < n_nodes) { g_counts[i] = 0; g_flag[i] = 0; }
}

// -------- flag queried nodes --------
__global__ void flag_kernel(const void* __restrict__ users, const void* __restrict__ items,
                            int B, int n_users) {
    const bool is64 = (g_is64 != 0);
    int i = blockIdx.x * blockDim.x + threadIdx.x;
    if (i < B) {
        g_flag[load_idx(users, i, is64)] = 1;
        g_flag[n_users + load_idx(items, i, is64)] = 1;
    }
}

// -------- histogram of destinations (streaming edge reads) --------
__global__ void hist_kernel(const void* __restrict__ dst, int n_edges) {
    const bool is64 = (g_is64 != 0);
    int stride = gridDim.x * blockDim.x;
    for (int e = blockIdx.x * blockDim.x + threadIdx.x; e < n_edges; e += stride)
        atomicAdd(&g_counts[load_idx_cs(dst, e, is64)], 1);
}

// ======== 3-phase parallel exclusive scan ========
__global__ void __launch_bounds__(SCAN_BLK)
scan_blocks_kernel(int n_nodes) {
    __shared__ int warp_tot[32];
    int tid  = threadIdx.x;
    int lane = tid & 31, wid = tid >> 5;
    int i = blockIdx.x * SCAN_BLK + tid;
    int v = (i < n_nodes) ? g_counts[i] : 0;

    int x = v;
    #pragma unroll
    for (int o = 1; o < 32; o <<= 1) {
        int t = __shfl_up_sync(0xffffffffu, x, o);
        if (lane >= o) x += t;
    }
    if (lane == 31) warp_tot[wid] = x;
    __syncthreads();
    if (wid == 0) {
        int w = warp_tot[lane];
        #pragma unroll
        for (int o = 1; o < 32; o <<= 1) {
            int t = __shfl_up_sync(0xffffffffu, w, o);
            if (lane >= o) w += t;
        }
        warp_tot[lane] = w;
    }
    __syncthreads();
    int base = wid ? warp_tot[wid - 1] : 0;
    int incl = base + x;
    if (i < n_nodes) g_counts[i] = incl - v;
    if (tid == SCAN_BLK - 1) g_part[blockIdx.x] = incl;
}

__global__ void __launch_bounds__(PARTS_MAX)
scan_parts_kernel(int nb, int n_nodes) {
    __shared__ int warp_tot[8];
    int tid = threadIdx.x, lane = tid & 31, wid = tid >> 5;
    int v = (tid < nb) ? g_part[tid] : 0;
    int x = v;
    #pragma unroll
    for (int o = 1; o < 32; o <<= 1) {
        int t = __shfl_up_sync(0xffffffffu, x, o);
        if (lane >= o) x += t;
    }
    if (lane == 31) warp_tot[wid] = x;
    __syncthreads();
    if (wid == 0 && lane < 8) {
        int w = warp_tot[lane];
        #pragma unroll
        for (int o = 1; o < 8; o <<= 1) {
            int t = __shfl_up_sync(0xffu, w, o);
            if (lane >= o) w += t;
        }
        warp_tot[lane] = w;
    }
    __syncthreads();
    int base = wid ? warp_tot[wid - 1] : 0;
    int incl = base + x;
    if (tid < nb) g_part[tid] = incl - v;
    if (tid == PARTS_MAX - 1) g_offsets[n_nodes] = incl;
}

__global__ void __launch_bounds__(SCAN_BLK)
scan_add_kernel(int n_nodes) {
    int i = blockIdx.x * SCAN_BLK + threadIdx.x;
    if (i < n_nodes) {
        int o = g_counts[i] + g_part[blockIdx.x];
        g_offsets[i] = o;
        g_cursor [i] = o;
    }
}

// -------- scatter edges into CSR slots (streaming edge reads) --------
__global__ void fill_kernel(const void* __restrict__ src, const void* __restrict__ dst,
                            const float* __restrict__ val, int n_edges) {
    const bool is64 = (g_is64 != 0);
    int stride = gridDim.x * blockDim.x;
    for (int e = blockIdx.x * blockDim.x + threadIdx.x; e < n_edges; e += stride) {
        int d = load_idx_cs(dst, e, is64);
        int pos = atomicAdd(&g_cursor[d], 1);
        g_csr[pos] = make_int2(load_idx_cs(src, e, is64), __float_as_int(__ldcs(val + e)));
    }
}

// -------- SpMM body: 2 edges per step, 8B gathers --------
// Lanes 0-15 gather even-edge rows, lanes 16-31 odd-edge rows.
// Lane owns dims [4*(lane&15) .. +3]; groups combined by shfl_xor(16) at end.
__device__ __forceinline__ float4 spmm_row2(const uint2* __restrict__ x8,
                                            int beg, int end, int lane) {
    const int g   = lane >> 4;
    const int l16 = lane & 15;
    float4 s = make_float4(0.f, 0.f, 0.f, 0.f);
    int e = beg;
    for (; e + 32 <= end; e += 32) {
        int2 ev = __ldcs(&g_csr[e + lane]);
        #pragma unroll
        for (int k = 0; k < 16; k++) {
            int k2 = 2 * k + g;
            int   sE = __shfl_sync(0xffffffffu, ev.x, k2);
            float vE = __int_as_float(__shfl_sync(0xffffffffu, ev.y, k2));
            uint2 d = x8[(size_t)sE * DIM8 + l16];
            float2 f0 = __half22float2(*(__half2*)&d.x);
            float2 f1 = __half22float2(*(__half2*)&d.y);
            s.x += vE * f0.x; s.y += vE * f0.y;
            s.z += vE * f1.x; s.w += vE * f1.y;
        }
    }
    int n = end - e;
    if (n > 0) {
        int2 ev = (lane < n) ? __ldcs(&g_csr[e + lane]) : make_int2(0, 0);
        int steps = (n + 1) >> 1;
        for (int k = 0; k < steps; k++) {
            int k2 = 2 * k + g;
            int sel = (k2 < n) ? k2 : 0;
            int   sE = __shfl_sync(0xffffffffu, ev.x, sel);
            float vE = __int_as_float(__shfl_sync(0xffffffffu, ev.y, sel));
            if (k2 >= n) vE = 0.f;
            uint2 d = x8[(size_t)sE * DIM8 + l16];
            float2 f0 = __half22float2(*(__half2*)&d.x);
            float2 f1 = __half22float2(*(__half2*)&d.y);
            s.x += vE * f0.x; s.y += vE * f0.y;
            s.z += vE * f1.x; s.w += vE * f1.y;
        }
    }
    // combine even/odd edge groups (all lanes end with full sums)
    s.x += __shfl_xor_sync(0xffffffffu, s.x, 16);
    s.y += __shfl_xor_sync(0xffffffffu, s.y, 16);
    s.z += __shfl_xor_sync(0xffffffffu, s.z, 16);
    s.w += __shfl_xor_sync(0xffffffffu, s.w, 16);
    return s;
}

// Layers 1-2: full graph, fp16 -> fp16. sel=0: A->B, sel=1: B->A.
__global__ void __launch_bounds__(256)
spmm_full_kernel(int sel, int n_nodes) {
    const uint2* __restrict__ x8 = (const uint2*)(sel ? h_bufB : h_bufA);
    uint2*       __restrict__ y8 = (uint2*)(sel ? h_bufA : h_bufB);
    int warp = (blockIdx.x * blockDim.x + threadIdx.x) >> 5;
    int lane = threadIdx.x & 31;
    if (warp >= n_nodes) return;
    float4 s = spmm_row2(x8, g_offsets[warp], g_offsets[warp + 1], lane);
    if (lane < 16) {
        __half2 o0 = __floats2half2_rn(s.x, s.y);
        __half2 o1 = __floats2half2_rn(s.z, s.w);
        uint2 o;
        o.x = *(unsigned int*)&o0;
        o.y = *(unsigned int*)&o1;
        y8[(size_t)warp * DIM8 + lane] = o;
    }
}

// Layer 3: flagged (queried) nodes only, fp16 -> fp32 g_l3.
__global__ void __launch_bounds__(256)
spmm_last_kernel(int n_nodes) {
    int warp = (blockIdx.x * blockDim.x + threadIdx.x) >> 5;
    int lane = threadIdx.x & 31;
    if (warp >= n_nodes) return;
    if (!g_flag[warp]) return;
    float4 s = spmm_row2((const uint2*)h_bufA, g_offsets[warp], g_offsets[warp + 1], lane);
    if (lane < 16)
        ((float4*)(g_l3 + (size_t)warp * DIM))[lane] = s;
}

// -------- final dot: acc = e0(inputs) + l1(bufB) + l2(bufA) + l3(g_l3) -------
__global__ void dot_kernel(const void* __restrict__ users, const void* __restrict__ items,
                           const float* __restrict__ ue, const float* __restrict__ ie,
                           float* __restrict__ out, int B, int n_users) {
    const bool is64 = (g_is64 != 0);
    int warp = (blockIdx.x * blockDim.x + threadIdx.x) >> 5;
    int lane = threadIdx.x & 31;
    if (warp >= B) return;
    int u  = load_idx(users, warp, is64);
    int ni = n_users + load_idx(items, warp, is64);

    float2 e0u = ((const float2*)ue)[(size_t)u * DIM2 + lane];
    float2 l1u = __half22float2(h_bufB[(size_t)u * DIM2 + lane]);
    float2 l2u = __half22float2(h_bufA[(size_t)u * DIM2 + lane]);
    float2 l3u = ((const float2*)(g_l3 + (size_t)u * DIM))[lane];
    float ax = e0u.x + l1u.x + l2u.x + l3u.x;
    float ay = e0u.y + l1u.y + l2u.y + l3u.y;

    float2 e0i = ((const float2*)ie)[(size_t)(ni - n_users) * DIM2 + lane];
    float2 l1i = __half22float2(h_bufB[(size_t)ni * DIM2 + lane]);
    float2 l2i = __half22float2(h_bufA[(size_t)ni * DIM2 + lane]);
    float2 l3i = ((const float2*)(g_l3 + (size_t)ni * DIM))[lane];
    float bx = e0i.x + l1i.x + l2i.x + l3i.x;
    float by = e0i.y + l1i.y + l2i.y + l3i.y;

    float p = ax * bx + ay * by;
    #pragma unroll
    for (int off = 16; off > 0; off >>= 1)
        p += __shfl_xor_sync(0xffffffffu, p, off);
    if (lane == 0) out[warp] = p * (1.0f / ((N_LAYERS + 1) * (N_LAYERS + 1)));
}

extern "C" void kernel_launch(void* const* d_in, const int* in_sizes, int n_in,
                              void* d_out, int out_size) {
    // ---- resolve input permutation from size fingerprint ----
    int iu, ii, is, id, iv, iue, iie;
    if ((long long)in_sizes[0] < (long long)in_sizes[2]) {
        iu = 0; ii = 1; is = 2; id = 3; iv = 4; iue = 5; iie = 6;   // dict order
    } else {
        id = 0; is = 1; iv = 2; iie = 3; ii = 4; iue = 5; iu = 6;   // alphabetical
    }
    const void*  users    = d_in[iu];
    const void*  items    = d_in[ii];
    const void*  edge_src = d_in[is];
    const void*  edge_dst = d_in[id];
    const float* edge_val = (const float*)d_in[iv];
    const float* user_emb = (const float*)d_in[iue];
    const float* item_emb = (const float*)d_in[iie];
    float* out = (float*)d_out;

    const int B       = in_sizes[iu];
    const int n_edges = in_sizes[is];
    const int n_users = in_sizes[iue] / DIM;
    const int n_items = in_sizes[iie] / DIM;
    const int n_nodes = n_users + n_items;
    const int nU2 = n_users * DIM / 2;
    const int nT2 = n_nodes * DIM / 2;
    const int nb  = (n_nodes + SCAN_BLK - 1) / SCAN_BLK;   // <= PARTS_MAX

    // dtype detection + init + flags + CSR build
    int nslots = n_edges / 2 < 4096 ? n_edges / 2 : 4096;
    detect_kernel<<<1, 1024>>>((const unsigned int*)edge_src, nslots);
    init_kernel<<<(nT2 + 255) / 256, 256>>>(user_emb, item_emb, nU2, nT2, n_nodes);
    flag_kernel<<<(B + 255) / 256, 256>>>(users, items, B, n_users);
    hist_kernel<<<2048, 256>>>(edge_dst, n_edges);
    scan_blocks_kernel<<<nb, SCAN_BLK>>>(n_nodes);
    scan_parts_kernel<<<1, PARTS_MAX>>>(nb, n_nodes);
    scan_add_kernel<<<nb, SCAN_BLK>>>(n_nodes);
    fill_kernel<<<2048, 256>>>(edge_src, edge_dst, edge_val, n_edges);

    // propagation: layers 1-2 full, layer 3 only queried nodes
    int spmm_grid = (n_nodes * 32 + 255) / 256;
    spmm_full_kernel<<<spmm_grid, 256>>>(0, n_nodes);   // l1: A -> B
    spmm_full_kernel<<<spmm_grid, 256>>>(1, n_nodes);   // l2: B -> A
    spmm_last_kernel<<<spmm_grid, 256>>>(n_nodes);      // l3: A -> g_l3 (flagged)

    // final dots (acc assembled in-kernel)
    dot_kernel<<<(B * 32 + 255) / 256, 256>>>(users, items, user_emb, item_emb,
                                              out, B, n_users);
}